// round 16
// baseline (speedup 1.0000x reference)
#include <cuda_runtime.h>
#include <math.h>
#include <stdint.h>

#define T_TOK 8192
#define HID   7168
#define NEXP  256

// ---- scratch ----
__device__ float g_scores[(size_t)T_TOK * NEXP];   // 8 MB sigmoid scores
__device__ int   g_nflag;
__device__ int   g_flags[T_TOK];

#define THETA   1e-6f
#define MARG_T  (3.0f * THETA)
#define MARG_G  (8.0f * THETA)

// ============================ helpers ============================
__device__ __forceinline__ void cpa16(uint32_t dst, const void* src) {
    asm volatile("cp.async.cg.shared.global [%0], [%1], 16;" :: "r"(dst), "l"(src));
}
__device__ __forceinline__ uint32_t smem_u32(const void* p) {
    uint32_t a;
    asm("{ .reg .u64 t; cvta.to.shared.u64 t, %1; cvt.u32.u64 %0, t; }" : "=r"(a) : "l"(p));
    return a;
}
#define CP_COMMIT() asm volatile("cp.async.commit_group;")
#define CP_WAIT2()  asm volatile("cp.async.wait_group 2;")

// d += a * b   (m16n8k16 bf16, fp32 accum)
#define MMAB(d, a, b) asm volatile( \
    "mma.sync.aligned.m16n8k16.row.col.f32.bf16.bf16.f32 " \
    "{%0,%1,%2,%3}, {%4,%5,%6,%7}, {%8,%9}, {%0,%1,%2,%3};" \
    : "+f"((d)[0]), "+f"((d)[1]), "+f"((d)[2]), "+f"((d)[3]) \
    : "r"((a)[0]), "r"((a)[1]), "r"((a)[2]), "r"((a)[3]), \
      "r"((b)[0]), "r"((b)[1]))

// exact 3-way bf16 split of a float2 (truncation; hi+mid+lo == x bitwise)
// PURE INTEGER + FSUB ops — zero F2F converts.
__device__ __forceinline__ void split2(float x0, float x1,
                                       uint32_t& hi, uint32_t& mid, uint32_t& lo) {
    uint32_t u0 = __float_as_uint(x0), u1 = __float_as_uint(x1);
    float h0 = __uint_as_float(u0 & 0xFFFF0000u);
    float h1 = __uint_as_float(u1 & 0xFFFF0000u);
    hi = __byte_perm(u0, u1, 0x7632);
    float d0 = x0 - h0, d1 = x1 - h1;
    uint32_t v0 = __float_as_uint(d0), v1 = __float_as_uint(d1);
    float m0 = __uint_as_float(v0 & 0xFFFF0000u);
    float m1 = __uint_as_float(v1 & 0xFFFF0000u);
    mid = __byte_perm(v0, v1, 0x7632);
    float l0 = d0 - m0, l1 = d1 - m1;
    lo = __byte_perm(__float_as_uint(l0), __float_as_uint(l1), 0x7632);
}

// ============================ GEMM config ============================
constexpr int BM = 128, BN = 128, BK = 32;
constexpr int NCHUNK  = HID / BK;      // 224
constexpr int LDT     = 36;            // padded smem row stride (floats)
constexpr int TILE_F  = 128 * LDT;
constexpr int STAGE_F = 2 * TILE_F;
constexpr int NSTAGE  = 4;
constexpr int SMEM_BYTES = NSTAGE * STAGE_F * 4;   // 147456

// ============================================================================
// K1: scores = sigmoid(x @ W^T), exact bf16 triple-split, 6 passes
//     (drop am*bl, al*bm ~2^-24-relative; rms logit impact ~5e-8)
// ============================================================================
__global__ __launch_bounds__(256, 1) void gemm_bf16x3_kernel(
    const float* __restrict__ x, const float* __restrict__ w)
{
    extern __shared__ float smem[];
    const uint32_t sbase = smem_u32(smem);

    const int tid  = threadIdx.x;
    const int lane = tid & 31;
    const int wid  = tid >> 5;
    const int g    = lane >> 2;
    const int tg   = lane & 3;

    const int n0 = (blockIdx.x & 1) * BN;
    const int m0 = (blockIdx.x >> 1) * BM;
    const int wm = (wid & 1) * 64;
    const int wn = (wid >> 1) * 32;

    const int lrow  = tid >> 1;
    const int lhalf = (tid & 1) * 16;
    const float* ga = x + (size_t)(m0 + lrow) * HID + lhalf;
    const float* gb = w + (size_t)(n0 + lrow) * HID + lhalf;
    const uint32_t sa = sbase + (uint32_t)(lrow * LDT + lhalf) * 4u;
    const uint32_t sb = sa + (uint32_t)TILE_F * 4u;

    auto issue = [&](int c) {
        const int s = c & 3;
        const uint32_t da = sa + (uint32_t)(s * STAGE_F) * 4u;
        const uint32_t db = sb + (uint32_t)(s * STAGE_F) * 4u;
        const float* pa = ga + c * BK;
        const float* pb = gb + c * BK;
#pragma unroll
        for (int q = 0; q < 4; ++q) {
            cpa16(da + q * 16, pa + q * 4);
            cpa16(db + q * 16, pb + q * 4);
        }
    };

    issue(0); CP_COMMIT();
    issue(1); CP_COMMIT();
    issue(2); CP_COMMIT();

    float accP[4][4][4], accS[4][4][4];
#pragma unroll
    for (int i = 0; i < 4; ++i)
#pragma unroll
        for (int j = 0; j < 4; ++j)
#pragma unroll
            for (int e = 0; e < 4; ++e) { accP[i][j][e] = 0.f; accS[i][j][e] = 0.f; }

#pragma unroll 1
    for (int c = 0; c < NCHUNK; ++c) {
        CP_WAIT2();
        __syncthreads();
        if (c + 3 < NCHUNK) issue(c + 3);
        CP_COMMIT();

        const float* As = smem + (c & 3) * STAGE_F;
        const float* Bs = As + TILE_F;

#pragma unroll
        for (int kk = 0; kk < 2; ++kk) {
            const int k0 = kk * 16;

            uint32_t ah[4][4], am[4][4], al[4][4];
#pragma unroll
            for (int i = 0; i < 4; ++i) {
                const float* ap = As + (wm + i * 16) * LDT + k0;
                float2 f0 = *(const float2*)(ap + g * LDT + tg * 2);
                float2 f1 = *(const float2*)(ap + (g + 8) * LDT + tg * 2);
                float2 f2 = *(const float2*)(ap + g * LDT + tg * 2 + 8);
                float2 f3 = *(const float2*)(ap + (g + 8) * LDT + tg * 2 + 8);
                split2(f0.x, f0.y, ah[i][0], am[i][0], al[i][0]);
                split2(f1.x, f1.y, ah[i][1], am[i][1], al[i][1]);
                split2(f2.x, f2.y, ah[i][2], am[i][2], al[i][2]);
                split2(f3.x, f3.y, ah[i][3], am[i][3], al[i][3]);
            }

            uint32_t bh[4][2], bm[4][2], bl[4][2];
#pragma unroll
            for (int j = 0; j < 4; ++j) {
                const float* bp = Bs + (wn + j * 8 + g) * LDT + k0;
                float2 f0 = *(const float2*)(bp + tg * 2);
                float2 f1 = *(const float2*)(bp + tg * 2 + 8);
                split2(f0.x, f0.y, bh[j][0], bm[j][0], bl[j][0]);
                split2(f1.x, f1.y, bh[j][1], bm[j][1], bl[j][1]);
            }

            // 6 passes
#pragma unroll
            for (int i = 0; i < 4; ++i)
#pragma unroll
                for (int j = 0; j < 4; ++j) MMAB(accP[i][j], ah[i], bh[j]);
#pragma unroll
            for (int i = 0; i < 4; ++i)
#pragma unroll
                for (int j = 0; j < 4; ++j) {
                    MMAB(accS[i][j], ah[i], bm[j]);
                    MMAB(accS[i][j], am[i], bh[j]);
                }
#pragma unroll
            for (int i = 0; i < 4; ++i)
#pragma unroll
                for (int j = 0; j < 4; ++j) {
                    MMAB(accS[i][j], am[i], bm[j]);
                    MMAB(accS[i][j], ah[i], bl[j]);
                    MMAB(accS[i][j], al[i], bh[j]);
                }
        }
    }

    // epilogue: merge, sigmoid, store
#pragma unroll
    for (int i = 0; i < 4; ++i) {
        const int r0 = m0 + wm + i * 16 + g;
#pragma unroll
        for (int j = 0; j < 4; ++j) {
            float* p0 = g_scores + (size_t)r0 * NEXP + n0 + wn + j * 8 + tg * 2;
            float* p1 = p0 + 8 * NEXP;
            float s0 = accP[i][j][0] + accS[i][j][0];
            float s1 = accP[i][j][1] + accS[i][j][1];
            float s2 = accP[i][j][2] + accS[i][j][2];
            float s3 = accP[i][j][3] + accS[i][j][3];
            float2 v0, v1;
            v0.x = 1.f / (1.f + expf(-s0));
            v0.y = 1.f / (1.f + expf(-s1));
            v1.x = 1.f / (1.f + expf(-s2));
            v1.y = 1.f / (1.f + expf(-s3));
            *(float2*)p0 = v0;
            *(float2*)p1 = v1;
        }
    }
}

// ============================================================================
__global__ void reset_kernel() { g_nflag = 0; }

// ============================================================================
// K2: gate on scores with margin checks; flag tight tokens
// ============================================================================
__global__ __launch_bounds__(256) void gate_margin_kernel(
    const float* __restrict__ bias,
    float* __restrict__ out, int out_size)
{
    const int wid = threadIdx.x >> 5;
    const int l   = threadIdx.x & 31;
    const int t   = blockIdx.x * 8 + wid;

    const float* srow = g_scores + (size_t)t * NEXP;
    float v[8];
#pragma unroll
    for (int k = 0; k < 8; ++k)
        v[k] = srow[k * 32 + l] + bias[k * 32 + l];

    float gsc[8];
#pragma unroll
    for (int k = 0; k < 8; ++k) {
        float m1 = v[k];
#pragma unroll
        for (int o = 16; o > 0; o >>= 1) m1 = fmaxf(m1, __shfl_xor_sync(0xffffffffu, m1, o));
        unsigned bal = __ballot_sync(0xffffffffu, v[k] == m1);
        int fl = __ffs(bal) - 1;
        float vx = (l == fl) ? -INFINITY : v[k];
#pragma unroll
        for (int o = 16; o > 0; o >>= 1) vx = fmaxf(vx, __shfl_xor_sync(0xffffffffu, vx, o));
        gsc[k] = m1 + vx;
    }

    unsigned keep = 0;
    float g4 = INFINITY;
#pragma unroll
    for (int r = 0; r < 4; ++r) {
        float best = -INFINITY; int bi = 0;
#pragma unroll
        for (int k = 0; k < 8; ++k) {
            bool tk = !((keep >> k) & 1u) && (gsc[k] > best);
            best = tk ? gsc[k] : best;
            bi   = tk ? k : bi;
        }
        keep |= 1u << bi;
        g4 = best;
    }
    float g5 = -INFINITY;
#pragma unroll
    for (int k = 0; k < 8; ++k)
        if (!((keep >> k) & 1u)) g5 = fmaxf(g5, gsc[k]);

    bool flag = (g4 - g5) < MARG_G;

    float cand[8];
#pragma unroll
    for (int k = 0; k < 8; ++k) cand[k] = ((keep >> k) & 1u) ? v[k] : -INFINITY;

    float sval[9]; int sel[9];
#pragma unroll
    for (int r = 0; r < 9; ++r) {
        float bv = cand[0]; int bk = 0;
#pragma unroll
        for (int k = 1; k < 8; ++k) {
            bool tk = cand[k] > bv;
            bv = tk ? cand[k] : bv;
            bk = tk ? k : bk;
        }
        int be = bk * 32 + l;
#pragma unroll
        for (int o = 16; o > 0; o >>= 1) {
            float ov = __shfl_xor_sync(0xffffffffu, bv, o);
            int   oe = __shfl_xor_sync(0xffffffffu, be, o);
            if (ov > bv || (ov == bv && oe < be)) { bv = ov; be = oe; }
        }
        sval[r] = bv; sel[r] = be;
        const int kk = be >> 5, ll = be & 31;
#pragma unroll
        for (int k = 0; k < 8; ++k)
            if (k == kk && l == ll) cand[k] = -INFINITY;
    }
#pragma unroll
    for (int r = 0; r < 8; ++r)
        flag = flag || ((sval[r] - sval[r + 1]) < MARG_T);

    if (l == 0) {
        if (flag) {
            int idx = atomicAdd(&g_nflag, 1);
            g_flags[idx] = t;
        }
        float wv[8], sw = 0.f;
#pragma unroll
        for (int r = 0; r < 8; ++r) { wv[r] = srow[sel[r]]; sw += wv[r]; }
        const float inv = 2.5f / (sw + 1e-20f);
        float4 w0 = make_float4(wv[0] * inv, wv[1] * inv, wv[2] * inv, wv[3] * inv);
        float4 w1 = make_float4(wv[4] * inv, wv[5] * inv, wv[6] * inv, wv[7] * inv);
        float4* wo = (float4*)(out + (size_t)t * 8);
        wo[0] = w0; wo[1] = w1;
        if (out_size >= 2 * T_TOK * 8) {
            float4 i0 = make_float4((float)sel[0], (float)sel[1], (float)sel[2], (float)sel[3]);
            float4 i1 = make_float4((float)sel[4], (float)sel[5], (float)sel[6], (float)sel[7]);
            float4* io = (float4*)(out + (size_t)T_TOK * 8 + (size_t)t * 8);
            io[0] = i0; io[1] = i1;
        }
    }
}

// ============================================================================
// K3: exact serial recompute + gate for flagged tokens (ascending-k chain)
//     with depth-2 register prefetch of W batches (arithmetic order unchanged)
// ============================================================================
__global__ __launch_bounds__(256) void fixup_kernel(
    const float* __restrict__ x, const float* __restrict__ w,
    const float* __restrict__ bias,
    float* __restrict__ out, int out_size)
{
    __shared__ float xs[HID];
    __shared__ float ss[NEXP];

    const int tid = threadIdx.x;
    const int nflag = g_nflag;
    constexpr int NB = HID / 32;     // 224 batches of 8 float4

    for (int fi = blockIdx.x; fi < nflag; fi += gridDim.x) {
        const int t = g_flags[fi];

        for (int i = tid; i < HID; i += 256)
            xs[i] = x[(size_t)t * HID + i];
        __syncthreads();

        {
            const float4* wr = (const float4*)(w + (size_t)tid * HID);
            float4 buf[3][8];
#pragma unroll
            for (int q = 0; q < 8; ++q) buf[0][q] = wr[q];
#pragma unroll
            for (int q = 0; q < 8; ++q) buf[1][q] = wr[8 + q];

            float acc = 0.f;
#pragma unroll 1
            for (int b = 0; b < NB; ++b) {
                const int cur = b % 3;
                if (b + 2 < NB) {
                    const int nxt = (b + 2) % 3;
#pragma unroll
                    for (int q = 0; q < 8; ++q) buf[nxt][q] = wr[(b + 2) * 8 + q];
                }
                const float* xq = xs + b * 32;
#pragma unroll
                for (int q = 0; q < 8; ++q) {
                    float4 f = buf[cur][q];
                    acc = fmaf(xq[q * 4 + 0], f.x, acc);
                    acc = fmaf(xq[q * 4 + 1], f.y, acc);
                    acc = fmaf(xq[q * 4 + 2], f.z, acc);
                    acc = fmaf(xq[q * 4 + 3], f.w, acc);
                }
            }
            ss[tid] = 1.f / (1.f + expf(-acc));
        }
        __syncthreads();

        if (tid < 32) {
            const int l = tid;
            float v[8];
#pragma unroll
            for (int k = 0; k < 8; ++k)
                v[k] = ss[k * 32 + l] + bias[k * 32 + l];

            float gsc[8];
#pragma unroll
            for (int k = 0; k < 8; ++k) {
                float m1 = v[k];
#pragma unroll
                for (int o = 16; o > 0; o >>= 1) m1 = fmaxf(m1, __shfl_xor_sync(0xffffffffu, m1, o));
                unsigned bal = __ballot_sync(0xffffffffu, v[k] == m1);
                int fl = __ffs(bal) - 1;
                float vx = (l == fl) ? -INFINITY : v[k];
#pragma unroll
                for (int o = 16; o > 0; o >>= 1) vx = fmaxf(vx, __shfl_xor_sync(0xffffffffu, vx, o));
                gsc[k] = m1 + vx;
            }
            unsigned keep = 0;
#pragma unroll
            for (int r = 0; r < 4; ++r) {
                float best = -INFINITY; int bi = 0;
#pragma unroll
                for (int k = 0; k < 8; ++k) {
                    bool tk = !((keep >> k) & 1u) && (gsc[k] > best);
                    best = tk ? gsc[k] : best;
                    bi   = tk ? k : bi;
                }
                keep |= 1u << bi;
            }
            float cand[8];
#pragma unroll
            for (int k = 0; k < 8; ++k) cand[k] = ((keep >> k) & 1u) ? v[k] : -INFINITY;

            int sel[8]; float wv[8];
#pragma unroll
            for (int r = 0; r < 8; ++r) {
                float bv = cand[0]; int bk = 0;
#pragma unroll
                for (int k = 1; k < 8; ++k) {
                    bool tk = cand[k] > bv;
                    bv = tk ? cand[k] : bv;
                    bk = tk ? k : bk;
                }
                int be = bk * 32 + l;
#pragma unroll
                for (int o = 16; o > 0; o >>= 1) {
                    float ov = __shfl_xor_sync(0xffffffffu, bv, o);
                    int   oe = __shfl_xor_sync(0xffffffffu, be, o);
                    if (ov > bv || (ov == bv && oe < be)) { bv = ov; be = oe; }
                }
                sel[r] = be;
                const int kk = be >> 5, ll = be & 31;
#pragma unroll
                for (int k = 0; k < 8; ++k)
                    if (k == kk && l == ll) cand[k] = -INFINITY;
            }
            if (l == 0) {
                float sw = 0.f;
#pragma unroll
                for (int r = 0; r < 8; ++r) { wv[r] = ss[sel[r]]; sw += wv[r]; }
                const float inv = 2.5f / (sw + 1e-20f);
                float* wo = out + (size_t)t * 8;
#pragma unroll
                for (int r = 0; r < 8; ++r) wo[r] = wv[r] * inv;
                if (out_size >= 2 * T_TOK * 8) {
                    float* io = out + (size_t)T_TOK * 8 + (size_t)t * 8;
#pragma unroll
                    for (int r = 0; r < 8; ++r) io[r] = (float)sel[r];
                }
            }
        }
        __syncthreads();
    }
}

// ============================================================================
extern "C" void kernel_launch(void* const* d_in, const int* in_sizes, int n_in,
                              void* d_out, int out_size)
{
    const float* x = nullptr; const float* w = nullptr; const float* b = nullptr;
    for (int i = 0; i < n_in; ++i) {
        long long sz = in_sizes[i];
        if (sz == (long long)T_TOK * HID) x = (const float*)d_in[i];
        else if (sz == (long long)NEXP * HID) w = (const float*)d_in[i];
        else if (sz == NEXP) b = (const float*)d_in[i];
    }
    float* out = (float*)d_out;

    cudaFuncSetAttribute(gemm_bf16x3_kernel,
                         cudaFuncAttributeMaxDynamicSharedMemorySize, SMEM_BYTES);

    reset_kernel<<<1, 1>>>();
    gemm_bf16x3_kernel<<<(T_TOK / BM) * (NEXP / BN), 256, SMEM_BYTES>>>(x, w);
    gate_margin_kernel<<<T_TOK / 8, 256>>>(b, out, out_size);
    fixup_kernel<<<256, 256>>>(x, w, b, out, out_size);
}

// round 17
// speedup vs baseline: 1.1603x; 1.1603x over previous
#include <cuda_runtime.h>
#include <math.h>
#include <stdint.h>

#define T_TOK 8192
#define HID   7168
#define NEXP  256

// ---- scratch ----
__device__ float g_scores[(size_t)T_TOK * NEXP];   // 8 MB sigmoid scores
__device__ int   g_nflag;
__device__ int   g_flags[T_TOK];

#define THETA   1e-6f
#define MARG_T  (3.0f * THETA)
#define MARG_G  (8.0f * THETA)

// ============================ helpers ============================
__device__ __forceinline__ void cpa16(uint32_t dst, const void* src) {
    asm volatile("cp.async.cg.shared.global [%0], [%1], 16;" :: "r"(dst), "l"(src));
}
__device__ __forceinline__ uint32_t smem_u32(const void* p) {
    uint32_t a;
    asm("{ .reg .u64 t; cvta.to.shared.u64 t, %1; cvt.u32.u64 %0, t; }" : "=r"(a) : "l"(p));
    return a;
}
#define CP_COMMIT() asm volatile("cp.async.commit_group;")
#define CP_WAIT2()  asm volatile("cp.async.wait_group 2;")

// d += a * b   (m16n8k16 bf16, fp32 accum)
#define MMAB(d, a, b) asm volatile( \
    "mma.sync.aligned.m16n8k16.row.col.f32.bf16.bf16.f32 " \
    "{%0,%1,%2,%3}, {%4,%5,%6,%7}, {%8,%9}, {%0,%1,%2,%3};" \
    : "+f"((d)[0]), "+f"((d)[1]), "+f"((d)[2]), "+f"((d)[3]) \
    : "r"((a)[0]), "r"((a)[1]), "r"((a)[2]), "r"((a)[3]), \
      "r"((b)[0]), "r"((b)[1]))

// exact 3-way bf16 split of a float2 (truncation; hi+mid+lo == x bitwise)
__device__ __forceinline__ void split2(float x0, float x1,
                                       uint32_t& hi, uint32_t& mid, uint32_t& lo) {
    uint32_t u0 = __float_as_uint(x0), u1 = __float_as_uint(x1);
    float h0 = __uint_as_float(u0 & 0xFFFF0000u);
    float h1 = __uint_as_float(u1 & 0xFFFF0000u);
    hi = __byte_perm(u0, u1, 0x7632);
    float d0 = x0 - h0, d1 = x1 - h1;
    uint32_t v0 = __float_as_uint(d0), v1 = __float_as_uint(d1);
    float m0 = __uint_as_float(v0 & 0xFFFF0000u);
    float m1 = __uint_as_float(v1 & 0xFFFF0000u);
    mid = __byte_perm(v0, v1, 0x7632);
    float l0 = d0 - m0, l1 = d1 - m1;
    lo = __byte_perm(__float_as_uint(l0), __float_as_uint(l1), 0x7632);
}

// ============================ GEMM config ============================
constexpr int BM = 128, BN = 128, BK = 32;
constexpr int NCHUNK  = HID / BK;      // 224
constexpr int LDT     = 36;            // padded smem row stride (floats)
constexpr int TILE_F  = 128 * LDT;
constexpr int STAGE_F = 2 * TILE_F;
constexpr int NSTAGE  = 4;
constexpr int SMEM_BYTES = NSTAGE * STAGE_F * 4;   // 147456

// ============================================================================
// K1: scores = sigmoid(x @ W^T), exact bf16 triple-split, 6 passes
// ============================================================================
__global__ __launch_bounds__(256, 1) void gemm_bf16x3_kernel(
    const float* __restrict__ x, const float* __restrict__ w)
{
    extern __shared__ float smem[];
    const uint32_t sbase = smem_u32(smem);

    const int tid  = threadIdx.x;
    const int lane = tid & 31;
    const int wid  = tid >> 5;
    const int g    = lane >> 2;
    const int tg   = lane & 3;

    const int n0 = (blockIdx.x & 1) * BN;
    const int m0 = (blockIdx.x >> 1) * BM;
    const int wm = (wid & 1) * 64;
    const int wn = (wid >> 1) * 32;

    const int lrow  = tid >> 1;
    const int lhalf = (tid & 1) * 16;
    const float* ga = x + (size_t)(m0 + lrow) * HID + lhalf;
    const float* gb = w + (size_t)(n0 + lrow) * HID + lhalf;
    const uint32_t sa = sbase + (uint32_t)(lrow * LDT + lhalf) * 4u;
    const uint32_t sb = sa + (uint32_t)TILE_F * 4u;

    auto issue = [&](int c) {
        const int s = c & 3;
        const uint32_t da = sa + (uint32_t)(s * STAGE_F) * 4u;
        const uint32_t db = sb + (uint32_t)(s * STAGE_F) * 4u;
        const float* pa = ga + c * BK;
        const float* pb = gb + c * BK;
#pragma unroll
        for (int q = 0; q < 4; ++q) {
            cpa16(da + q * 16, pa + q * 4);
            cpa16(db + q * 16, pb + q * 4);
        }
    };

    issue(0); CP_COMMIT();
    issue(1); CP_COMMIT();
    issue(2); CP_COMMIT();

    float accP[4][4][4], accS[4][4][4];
#pragma unroll
    for (int i = 0; i < 4; ++i)
#pragma unroll
        for (int j = 0; j < 4; ++j)
#pragma unroll
            for (int e = 0; e < 4; ++e) { accP[i][j][e] = 0.f; accS[i][j][e] = 0.f; }

#pragma unroll 1
    for (int c = 0; c < NCHUNK; ++c) {
        CP_WAIT2();
        __syncthreads();
        if (c + 3 < NCHUNK) issue(c + 3);
        CP_COMMIT();

        const float* As = smem + (c & 3) * STAGE_F;
        const float* Bs = As + TILE_F;

#pragma unroll
        for (int kk = 0; kk < 2; ++kk) {
            const int k0 = kk * 16;

            uint32_t ah[4][4], am[4][4], al[4][4];
#pragma unroll
            for (int i = 0; i < 4; ++i) {
                const float* ap = As + (wm + i * 16) * LDT + k0;
                float2 f0 = *(const float2*)(ap + g * LDT + tg * 2);
                float2 f1 = *(const float2*)(ap + (g + 8) * LDT + tg * 2);
                float2 f2 = *(const float2*)(ap + g * LDT + tg * 2 + 8);
                float2 f3 = *(const float2*)(ap + (g + 8) * LDT + tg * 2 + 8);
                split2(f0.x, f0.y, ah[i][0], am[i][0], al[i][0]);
                split2(f1.x, f1.y, ah[i][1], am[i][1], al[i][1]);
                split2(f2.x, f2.y, ah[i][2], am[i][2], al[i][2]);
                split2(f3.x, f3.y, ah[i][3], am[i][3], al[i][3]);
            }

            uint32_t bh[4][2], bm[4][2], bl[4][2];
#pragma unroll
            for (int j = 0; j < 4; ++j) {
                const float* bp = Bs + (wn + j * 8 + g) * LDT + k0;
                float2 f0 = *(const float2*)(bp + tg * 2);
                float2 f1 = *(const float2*)(bp + tg * 2 + 8);
                split2(f0.x, f0.y, bh[j][0], bm[j][0], bl[j][0]);
                split2(f1.x, f1.y, bh[j][1], bm[j][1], bl[j][1]);
            }

            // 6 passes
#pragma unroll
            for (int i = 0; i < 4; ++i)
#pragma unroll
                for (int j = 0; j < 4; ++j) MMAB(accP[i][j], ah[i], bh[j]);
#pragma unroll
            for (int i = 0; i < 4; ++i)
#pragma unroll
                for (int j = 0; j < 4; ++j) {
                    MMAB(accS[i][j], ah[i], bm[j]);
                    MMAB(accS[i][j], am[i], bh[j]);
                }
#pragma unroll
            for (int i = 0; i < 4; ++i)
#pragma unroll
                for (int j = 0; j < 4; ++j) {
                    MMAB(accS[i][j], am[i], bm[j]);
                    MMAB(accS[i][j], ah[i], bl[j]);
                    MMAB(accS[i][j], al[i], bh[j]);
                }
        }
    }

    // epilogue: merge, sigmoid, store
#pragma unroll
    for (int i = 0; i < 4; ++i) {
        const int r0 = m0 + wm + i * 16 + g;
#pragma unroll
        for (int j = 0; j < 4; ++j) {
            float* p0 = g_scores + (size_t)r0 * NEXP + n0 + wn + j * 8 + tg * 2;
            float* p1 = p0 + 8 * NEXP;
            float s0 = accP[i][j][0] + accS[i][j][0];
            float s1 = accP[i][j][1] + accS[i][j][1];
            float s2 = accP[i][j][2] + accS[i][j][2];
            float s3 = accP[i][j][3] + accS[i][j][3];
            float2 v0, v1;
            v0.x = 1.f / (1.f + expf(-s0));
            v0.y = 1.f / (1.f + expf(-s1));
            v1.x = 1.f / (1.f + expf(-s2));
            v1.y = 1.f / (1.f + expf(-s3));
            *(float2*)p0 = v0;
            *(float2*)p1 = v1;
        }
    }
}

// ============================================================================
__global__ void reset_kernel() { g_nflag = 0; }

// ============================================================================
// K2: gate on scores with margin checks; flag tight tokens
// ============================================================================
__global__ __launch_bounds__(256) void gate_margin_kernel(
    const float* __restrict__ bias,
    float* __restrict__ out, int out_size)
{
    const int wid = threadIdx.x >> 5;
    const int l   = threadIdx.x & 31;
    const int t   = blockIdx.x * 8 + wid;

    const float* srow = g_scores + (size_t)t * NEXP;
    float v[8];
#pragma unroll
    for (int k = 0; k < 8; ++k)
        v[k] = srow[k * 32 + l] + bias[k * 32 + l];

    float gsc[8];
#pragma unroll
    for (int k = 0; k < 8; ++k) {
        float m1 = v[k];
#pragma unroll
        for (int o = 16; o > 0; o >>= 1) m1 = fmaxf(m1, __shfl_xor_sync(0xffffffffu, m1, o));
        unsigned bal = __ballot_sync(0xffffffffu, v[k] == m1);
        int fl = __ffs(bal) - 1;
        float vx = (l == fl) ? -INFINITY : v[k];
#pragma unroll
        for (int o = 16; o > 0; o >>= 1) vx = fmaxf(vx, __shfl_xor_sync(0xffffffffu, vx, o));
        gsc[k] = m1 + vx;
    }

    unsigned keep = 0;
    float g4 = INFINITY;
#pragma unroll
    for (int r = 0; r < 4; ++r) {
        float best = -INFINITY; int bi = 0;
#pragma unroll
        for (int k = 0; k < 8; ++k) {
            bool tk = !((keep >> k) & 1u) && (gsc[k] > best);
            best = tk ? gsc[k] : best;
            bi   = tk ? k : bi;
        }
        keep |= 1u << bi;
        g4 = best;
    }
    float g5 = -INFINITY;
#pragma unroll
    for (int k = 0; k < 8; ++k)
        if (!((keep >> k) & 1u)) g5 = fmaxf(g5, gsc[k]);

    bool flag = (g4 - g5) < MARG_G;

    float cand[8];
#pragma unroll
    for (int k = 0; k < 8; ++k) cand[k] = ((keep >> k) & 1u) ? v[k] : -INFINITY;

    float sval[9]; int sel[9];
#pragma unroll
    for (int r = 0; r < 9; ++r) {
        float bv = cand[0]; int bk = 0;
#pragma unroll
        for (int k = 1; k < 8; ++k) {
            bool tk = cand[k] > bv;
            bv = tk ? cand[k] : bv;
            bk = tk ? k : bk;
        }
        int be = bk * 32 + l;
#pragma unroll
        for (int o = 16; o > 0; o >>= 1) {
            float ov = __shfl_xor_sync(0xffffffffu, bv, o);
            int   oe = __shfl_xor_sync(0xffffffffu, be, o);
            if (ov > bv || (ov == bv && oe < be)) { bv = ov; be = oe; }
        }
        sval[r] = bv; sel[r] = be;
        const int kk = be >> 5, ll = be & 31;
#pragma unroll
        for (int k = 0; k < 8; ++k)
            if (k == kk && l == ll) cand[k] = -INFINITY;
    }
#pragma unroll
    for (int r = 0; r < 8; ++r)
        flag = flag || ((sval[r] - sval[r + 1]) < MARG_T);

    if (l == 0) {
        if (flag) {
            int idx = atomicAdd(&g_nflag, 1);
            g_flags[idx] = t;
        }
        float wv[8], sw = 0.f;
#pragma unroll
        for (int r = 0; r < 8; ++r) { wv[r] = srow[sel[r]]; sw += wv[r]; }
        const float inv = 2.5f / (sw + 1e-20f);
        float4 w0 = make_float4(wv[0] * inv, wv[1] * inv, wv[2] * inv, wv[3] * inv);
        float4 w1 = make_float4(wv[4] * inv, wv[5] * inv, wv[6] * inv, wv[7] * inv);
        float4* wo = (float4*)(out + (size_t)t * 8);
        wo[0] = w0; wo[1] = w1;
        if (out_size >= 2 * T_TOK * 8) {
            float4 i0 = make_float4((float)sel[0], (float)sel[1], (float)sel[2], (float)sel[3]);
            float4 i1 = make_float4((float)sel[4], (float)sel[5], (float)sel[6], (float)sel[7]);
            float4* io = (float4*)(out + (size_t)T_TOK * 8 + (size_t)t * 8);
            io[0] = i0; io[1] = i1;
        }
    }
}

// ============================================================================
// K3: exact serial recompute + gate for flagged tokens (ascending-k chain)
//     W streamed via STATIC even/odd register double buffer (no dynamic
//     indexing -> no local-memory demotion). Arithmetic order unchanged.
// ============================================================================
__global__ __launch_bounds__(256) void fixup_kernel(
    const float* __restrict__ x, const float* __restrict__ w,
    const float* __restrict__ bias,
    float* __restrict__ out, int out_size)
{
    __shared__ float xs[HID];
    __shared__ float ss[NEXP];

    const int tid = threadIdx.x;
    const int nflag = g_nflag;
    constexpr int NB = HID / 32;     // 224 batches of 8 float4 (even)

    for (int fi = blockIdx.x; fi < nflag; fi += gridDim.x) {
        const int t = g_flags[fi];

        for (int i = tid; i < HID; i += 256)
            xs[i] = x[(size_t)t * HID + i];
        __syncthreads();

        {
            const float4* wr = (const float4*)(w + (size_t)tid * HID);
            float4 bA[8], bB[8];
#pragma unroll
            for (int q = 0; q < 8; ++q) bA[q] = wr[q];

            float acc = 0.f;
#pragma unroll 1
            for (int b = 0; b < NB; b += 2) {
                // prefetch batch b+1 into bB (static regs)
#pragma unroll
                for (int q = 0; q < 8; ++q) bB[q] = wr[(b + 1) * 8 + q];
                const float* xq0 = xs + b * 32;
#pragma unroll
                for (int q = 0; q < 8; ++q) {
                    float4 f = bA[q];
                    acc = fmaf(xq0[q * 4 + 0], f.x, acc);
                    acc = fmaf(xq0[q * 4 + 1], f.y, acc);
                    acc = fmaf(xq0[q * 4 + 2], f.z, acc);
                    acc = fmaf(xq0[q * 4 + 3], f.w, acc);
                }
                // prefetch batch b+2 into bA
                if (b + 2 < NB) {
#pragma unroll
                    for (int q = 0; q < 8; ++q) bA[q] = wr[(b + 2) * 8 + q];
                }
                const float* xq1 = xs + (b + 1) * 32;
#pragma unroll
                for (int q = 0; q < 8; ++q) {
                    float4 f = bB[q];
                    acc = fmaf(xq1[q * 4 + 0], f.x, acc);
                    acc = fmaf(xq1[q * 4 + 1], f.y, acc);
                    acc = fmaf(xq1[q * 4 + 2], f.z, acc);
                    acc = fmaf(xq1[q * 4 + 3], f.w, acc);
                }
            }
            ss[tid] = 1.f / (1.f + expf(-acc));
        }
        __syncthreads();

        if (tid < 32) {
            const int l = tid;
            float v[8];
#pragma unroll
            for (int k = 0; k < 8; ++k)
                v[k] = ss[k * 32 + l] + bias[k * 32 + l];

            float gsc[8];
#pragma unroll
            for (int k = 0; k < 8; ++k) {
                float m1 = v[k];
#pragma unroll
                for (int o = 16; o > 0; o >>= 1) m1 = fmaxf(m1, __shfl_xor_sync(0xffffffffu, m1, o));
                unsigned bal = __ballot_sync(0xffffffffu, v[k] == m1);
                int fl = __ffs(bal) - 1;
                float vx = (l == fl) ? -INFINITY : v[k];
#pragma unroll
                for (int o = 16; o > 0; o >>= 1) vx = fmaxf(vx, __shfl_xor_sync(0xffffffffu, vx, o));
                gsc[k] = m1 + vx;
            }
            unsigned keep = 0;
#pragma unroll
            for (int r = 0; r < 4; ++r) {
                float best = -INFINITY; int bi = 0;
#pragma unroll
                for (int k = 0; k < 8; ++k) {
                    bool tk = !((keep >> k) & 1u) && (gsc[k] > best);
                    best = tk ? gsc[k] : best;
                    bi   = tk ? k : bi;
                }
                keep |= 1u << bi;
            }
            float cand[8];
#pragma unroll
            for (int k = 0; k < 8; ++k) cand[k] = ((keep >> k) & 1u) ? v[k] : -INFINITY;

            int sel[8]; float wv[8];
#pragma unroll
            for (int r = 0; r < 8; ++r) {
                float bv = cand[0]; int bk = 0;
#pragma unroll
                for (int k = 1; k < 8; ++k) {
                    bool tk = cand[k] > bv;
                    bv = tk ? cand[k] : bv;
                    bk = tk ? k : bk;
                }
                int be = bk * 32 + l;
#pragma unroll
                for (int o = 16; o > 0; o >>= 1) {
                    float ov = __shfl_xor_sync(0xffffffffu, bv, o);
                    int   oe = __shfl_xor_sync(0xffffffffu, be, o);
                    if (ov > bv || (ov == bv && oe < be)) { bv = ov; be = oe; }
                }
                sel[r] = be;
                const int kk = be >> 5, ll = be & 31;
#pragma unroll
                for (int k = 0; k < 8; ++k)
                    if (k == kk && l == ll) cand[k] = -INFINITY;
            }
            if (l == 0) {
                float sw = 0.f;
#pragma unroll
                for (int r = 0; r < 8; ++r) { wv[r] = ss[sel[r]]; sw += wv[r]; }
                const float inv = 2.5f / (sw + 1e-20f);
                float* wo = out + (size_t)t * 8;
#pragma unroll
                for (int r = 0; r < 8; ++r) wo[r] = wv[r] * inv;
                if (out_size >= 2 * T_TOK * 8) {
                    float* io = out + (size_t)T_TOK * 8 + (size_t)t * 8;
#pragma unroll
                    for (int r = 0; r < 8; ++r) io[r] = (float)sel[r];
                }
            }
        }
        __syncthreads();
    }
}

// ============================================================================
extern "C" void kernel_launch(void* const* d_in, const int* in_sizes, int n_in,
                              void* d_out, int out_size)
{
    const float* x = nullptr; const float* w = nullptr; const float* b = nullptr;
    for (int i = 0; i < n_in; ++i) {
        long long sz = in_sizes[i];
        if (sz == (long long)T_TOK * HID) x = (const float*)d_in[i];
        else if (sz == (long long)NEXP * HID) w = (const float*)d_in[i];
        else if (sz == NEXP) b = (const float*)d_in[i];
    }
    float* out = (float*)d_out;

    cudaFuncSetAttribute(gemm_bf16x3_kernel,
                         cudaFuncAttributeMaxDynamicSharedMemorySize, SMEM_BYTES);

    reset_kernel<<<1, 1>>>();
    gemm_bf16x3_kernel<<<(T_TOK / BM) * (NEXP / BN), 256, SMEM_BYTES>>>(x, w);
    gate_margin_kernel<<<T_TOK / 8, 256>>>(b, out, out_size);
    fixup_kernel<<<256, 256>>>(x, w, b, out, out_size);
}